// round 2
// baseline (speedup 1.0000x reference)
#include <cuda_runtime.h>
#include <cstdint>

// ---------------------------------------------------------------------------
// Problem constants (B=1)
// ---------------------------------------------------------------------------
#define Lq   2048
#define Edim 4096
#define Hh   32
#define Nn   32
#define HRd  1024
#define DATT 32
#define DD   16
#define INTD 1024

// ---------------------------------------------------------------------------
// Scratch (static device globals; no allocation allowed)
// ---------------------------------------------------------------------------
__device__ float g_hr  [Lq * HRd];
__device__ float g_q   [Lq * HRd];
__device__ float g_k   [Lq * HRd];
__device__ float g_v   [Lq * HRd];
__device__ float g_attn[Lq * HRd];
__device__ float g_ln  [Lq * HRd];
__device__ float g_ff1 [Lq * 2 * HRd];
__device__ float g_hid [Lq * Edim];
__device__ float g_mid [Lq * INTD];
__device__ float g_raw [Lq * Nn * Hh * DD];   // 2048 x 16384
__device__ float g_cos1[Lq * DATT];
__device__ float g_sin1[Lq * DATT];
__device__ float g_cos2[Lq * DD];
__device__ float g_sin2[Lq * DD];

// ---------------------------------------------------------------------------
// RoPE tables (match reference fp32 math: inv = 1/theta^(2t/dim), f = l*inv)
// ---------------------------------------------------------------------------
__global__ void rope_tables_kernel(float* __restrict__ c1, float* __restrict__ s1,
                                   float* __restrict__ c2, float* __restrict__ s2)
{
    int idx = blockIdx.x * blockDim.x + threadIdx.x;
    if (idx < Lq * DATT) {
        int l = idx / DATT, d = idx % DATT;
        float inv = 1.0f / powf(10000.0f, (float)(2 * (d & 15)) / 32.0f);
        float f = (float)l * inv;
        c1[idx] = cosf(f);
        s1[idx] = sinf(f);
    }
    if (idx < Lq * DD) {
        int l = idx / DD, d = idx % DD;
        float inv = 1.0f / powf(10000.0f, (float)(2 * (d & 7)) / 16.0f);
        float f = (float)l * inv;
        c2[idx] = cosf(f);
        s2[idx] = sinf(f);
    }
}

// ---------------------------------------------------------------------------
// SGEMM (NT): C[M,N] = act(A[M,K] @ B[N,K]^T + bias) + resid
// 128x128 block tile, BK=16, 256 threads, 8x8 per-thread tile,
// double-buffered smem (one __syncthreads per K-tile).
// Requires M%128==0, N%128==0, K%32==0 (true for every call here).
// act: 0 = none, 1 = exact GELU, 2 = SiLU
// ---------------------------------------------------------------------------
__global__ void __launch_bounds__(256)
sgemm_nt_kernel(const float* __restrict__ A, const float* __restrict__ B,
                const float* __restrict__ bias, const float* __restrict__ resid,
                float* __restrict__ C, int M, int N, int K, int act)
{
    const int BM = 128, BN = 128, BK = 16;
    __shared__ float As[2][BK][BM];
    __shared__ float Bs[2][BK][BN];

    const int tid = threadIdx.x;
    const int bm = blockIdx.y * BM;
    const int bn = blockIdx.x * BN;
    const int ty = tid / 16;          // 0..15
    const int tx = tid % 16;          // 0..15

    const int lr = tid / 4;           // 0..63
    const int lc = (tid % 4) * 4;     // 0,4,8,12

    const float* Aptr = A + (size_t)(bm + lr) * K + lc;     // rows lr, lr+64
    const float* Bptr = B + (size_t)(bn + lr) * K + lc;

    float acc[8][8];
#pragma unroll
    for (int i = 0; i < 8; ++i)
#pragma unroll
        for (int j = 0; j < 8; ++j) acc[i][j] = 0.0f;

    const int T = K / BK;

    // prefetch tile 0 into regs
    float4 pa0 = *reinterpret_cast<const float4*>(Aptr);
    float4 pa1 = *reinterpret_cast<const float4*>(Aptr + (size_t)64 * K);
    float4 pb0 = *reinterpret_cast<const float4*>(Bptr);
    float4 pb1 = *reinterpret_cast<const float4*>(Bptr + (size_t)64 * K);

    int buf = 0;
    // store tile 0
    As[0][lc + 0][lr] = pa0.x; As[0][lc + 1][lr] = pa0.y;
    As[0][lc + 2][lr] = pa0.z; As[0][lc + 3][lr] = pa0.w;
    As[0][lc + 0][lr + 64] = pa1.x; As[0][lc + 1][lr + 64] = pa1.y;
    As[0][lc + 2][lr + 64] = pa1.z; As[0][lc + 3][lr + 64] = pa1.w;
    Bs[0][lc + 0][lr] = pb0.x; Bs[0][lc + 1][lr] = pb0.y;
    Bs[0][lc + 2][lr] = pb0.z; Bs[0][lc + 3][lr] = pb0.w;
    Bs[0][lc + 0][lr + 64] = pb1.x; Bs[0][lc + 1][lr + 64] = pb1.y;
    Bs[0][lc + 2][lr + 64] = pb1.z; Bs[0][lc + 3][lr + 64] = pb1.w;
    __syncthreads();

    for (int t = 0; t < T; ++t) {
        // prefetch next tile into regs (overlaps with compute below)
        if (t + 1 < T) {
            const float* An = Aptr + (t + 1) * BK;
            const float* Bn = Bptr + (t + 1) * BK;
            pa0 = *reinterpret_cast<const float4*>(An);
            pa1 = *reinterpret_cast<const float4*>(An + (size_t)64 * K);
            pb0 = *reinterpret_cast<const float4*>(Bn);
            pb1 = *reinterpret_cast<const float4*>(Bn + (size_t)64 * K);
        }

#pragma unroll
        for (int kk = 0; kk < BK; ++kk) {
            float ra[8], rb[8];
#pragma unroll
            for (int i = 0; i < 8; ++i) ra[i] = As[buf][kk][ty * 8 + i];
#pragma unroll
            for (int j = 0; j < 8; ++j) rb[j] = Bs[buf][kk][tx * 8 + j];
#pragma unroll
            for (int i = 0; i < 8; ++i)
#pragma unroll
                for (int j = 0; j < 8; ++j) acc[i][j] += ra[i] * rb[j];
        }

        if (t + 1 < T) {
            int nb = buf ^ 1;
            As[nb][lc + 0][lr] = pa0.x; As[nb][lc + 1][lr] = pa0.y;
            As[nb][lc + 2][lr] = pa0.z; As[nb][lc + 3][lr] = pa0.w;
            As[nb][lc + 0][lr + 64] = pa1.x; As[nb][lc + 1][lr + 64] = pa1.y;
            As[nb][lc + 2][lr + 64] = pa1.z; As[nb][lc + 3][lr + 64] = pa1.w;
            Bs[nb][lc + 0][lr] = pb0.x; Bs[nb][lc + 1][lr] = pb0.y;
            Bs[nb][lc + 2][lr] = pb0.z; Bs[nb][lc + 3][lr] = pb0.w;
            Bs[nb][lc + 0][lr + 64] = pb1.x; Bs[nb][lc + 1][lr + 64] = pb1.y;
            Bs[nb][lc + 2][lr + 64] = pb1.z; Bs[nb][lc + 3][lr + 64] = pb1.w;
            __syncthreads();
            buf = nb;
        }
    }

#pragma unroll
    for (int i = 0; i < 8; ++i) {
        int m = bm + ty * 8 + i;
#pragma unroll
        for (int j = 0; j < 8; ++j) {
            int n = bn + tx * 8 + j;
            float v = acc[i][j];
            if (bias) v += bias[n];
            if (act == 1) {                 // exact GELU
                v = 0.5f * v * (1.0f + erff(v * 0.7071067811865475f));
            } else if (act == 2) {          // SiLU
                v = v / (1.0f + expf(-v));
            }
            if (resid) v += resid[(size_t)m * N + n];
            C[(size_t)m * N + n] = v;
        }
    }
}

// ---------------------------------------------------------------------------
// RoPE on q,k (head dim 32), in place.  One thread per (l, head, pair<16).
// cos[d] == cos[d+16] (emb is concat(freqs,freqs)).
// ---------------------------------------------------------------------------
__global__ void rope1_kernel(float* __restrict__ q, float* __restrict__ k,
                             const float* __restrict__ c1, const float* __restrict__ s1)
{
    int idx = blockIdx.x * blockDim.x + threadIdx.x;       // L * 512
    if (idx >= Lq * (HRd / 2)) return;
    int l = idx >> 9;
    int c = idx & 511;
    int h = c >> 4;
    int d = c & 15;
    int base = l * HRd + h * DATT;
    float cv = c1[l * DATT + d];
    float sv = s1[l * DATT + d];

    float a  = q[base + d];
    float b  = q[base + d + 16];
    q[base + d]      = a * cv - b * sv;
    q[base + d + 16] = b * cv + a * sv;

    float a2 = k[base + d];
    float b2 = k[base + d + 16];
    k[base + d]      = a2 * cv - b2 * sv;
    k[base + d + 16] = b2 * cv + a2 * sv;
}

// ---------------------------------------------------------------------------
// Causal flash attention, d=32, thread-per-query online softmax.
// grid = (L/64, H), block = 64.  Q,K,V,O layout: [L][H*32].
// ---------------------------------------------------------------------------
__global__ void __launch_bounds__(64)
attn_kernel(const float* __restrict__ Q, const float* __restrict__ Kg,
            const float* __restrict__ Vg, float* __restrict__ O)
{
    __shared__ float Ks[64][32];
    __shared__ float Vs[64][32];

    const int h  = blockIdx.y;
    const int qb = blockIdx.x;
    const int t  = threadIdx.x;
    const int qrow = qb * 64 + t;

    float qreg[32], acc[32];
    const float* qp = Q + (size_t)qrow * HRd + h * DATT;
#pragma unroll
    for (int d = 0; d < 32; ++d) { qreg[d] = qp[d]; acc[d] = 0.0f; }

    float m = -1e30f, lsum = 0.0f;
    const float scale = 0.17677669529663687f;   // 1/sqrt(32)

    for (int kt = 0; kt <= qb; ++kt) {
        for (int idx = t; idx < 64 * 8; idx += 64) {
            int r  = idx / 8;
            int c4 = (idx % 8) * 4;
            size_t g = (size_t)(kt * 64 + r) * HRd + h * DATT + c4;
            *reinterpret_cast<float4*>(&Ks[r][c4]) = *reinterpret_cast<const float4*>(&Kg[g]);
            *reinterpret_cast<float4*>(&Vs[r][c4]) = *reinterpret_cast<const float4*>(&Vg[g]);
        }
        __syncthreads();

        const int kmax = (kt == qb) ? (t + 1) : 64;
        for (int kk = 0; kk < kmax; ++kk) {
            float s = 0.0f;
#pragma unroll
            for (int d = 0; d < 32; ++d) s += qreg[d] * Ks[kk][d];
            s *= scale;
            float mnew = fmaxf(m, s);
            float corr = __expf(m - mnew);
            float p    = __expf(s - mnew);
            lsum = lsum * corr + p;
#pragma unroll
            for (int d = 0; d < 32; ++d) acc[d] = acc[d] * corr + p * Vs[kk][d];
            m = mnew;
        }
        __syncthreads();
    }

    float inv = 1.0f / lsum;
    float* op = O + (size_t)qrow * HRd + h * DATT;
#pragma unroll
    for (int d = 0; d < 32; ++d) op[d] = acc[d] * inv;
}

// ---------------------------------------------------------------------------
// LayerNorm over last dim (1024).  grid = L, block = 256.
// ---------------------------------------------------------------------------
__global__ void __launch_bounds__(256)
ln_kernel(const float* __restrict__ X, const float* __restrict__ w,
          const float* __restrict__ b, float* __restrict__ Y)
{
    __shared__ float red[256];
    const int row = blockIdx.x;
    const float* xr = X + (size_t)row * HRd;

    float s = 0.0f;
    for (int i = threadIdx.x; i < HRd; i += 256) s += xr[i];
    red[threadIdx.x] = s; __syncthreads();
    for (int st = 128; st > 0; st >>= 1) {
        if (threadIdx.x < st) red[threadIdx.x] += red[threadIdx.x + st];
        __syncthreads();
    }
    float mu = red[0] / (float)HRd;
    __syncthreads();

    float vs = 0.0f;
    for (int i = threadIdx.x; i < HRd; i += 256) { float d = xr[i] - mu; vs += d * d; }
    red[threadIdx.x] = vs; __syncthreads();
    for (int st = 128; st > 0; st >>= 1) {
        if (threadIdx.x < st) red[threadIdx.x] += red[threadIdx.x + st];
        __syncthreads();
    }
    float rstd = rsqrtf(red[0] / (float)HRd + 1e-5f);

    for (int i = threadIdx.x; i < HRd; i += 256)
        Y[(size_t)row * HRd + i] = (xr[i] - mu) * rstd * w[i] + b[i];
}

// ---------------------------------------------------------------------------
// Second RoPE (dim 16) fused with the [L, N*H*16] -> [N,H,L,16] permute.
// One thread per pair: idx = (r*2048 + l)*8 + d, r = n*H+h, d in [0,8).
// ---------------------------------------------------------------------------
__global__ void rope2_out_kernel(const float* __restrict__ P,
                                 const float* __restrict__ c2, const float* __restrict__ s2,
                                 float* __restrict__ out)
{
    int idx = blockIdx.x * blockDim.x + threadIdx.x;
    if (idx >= (Nn * Hh) * Lq * (DD / 2)) return;
    int d = idx & 7;
    int l = (idx >> 3) & (Lq - 1);
    int r = idx >> 14;                               // n*H + h, 0..1023

    const float* p = P + (size_t)l * (Nn * Hh * DD) + r * DD;
    float a = p[d], b = p[d + 8];
    float cv = c2[l * DD + d];
    float sv = s2[l * DD + d];

    size_t o = ((size_t)r * Lq + l) * DD;
    out[o + d]     = a * cv - b * sv;
    out[o + d + 8] = b * cv + a * sv;
}

// ---------------------------------------------------------------------------
// Launch
// ---------------------------------------------------------------------------
static void sgemm(const float* A, const float* B, const float* bias,
                  const float* resid, float* C, int M, int N, int K, int act)
{
    dim3 grid(N / 128, M / 128);
    sgemm_nt_kernel<<<grid, 256>>>(A, B, bias, resid, C, M, N, K, act);
}

extern "C" void kernel_launch(void* const* d_in, const int* in_sizes, int n_in,
                              void* d_out, int out_size)
{
    const float* x      = (const float*)d_in[0];
    const float* Wi     = (const float*)d_in[1];
    const float* Wq     = (const float*)d_in[2];
    const float* Wk     = (const float*)d_in[3];
    const float* Wv     = (const float*)d_in[4];
    const float* ln1_w  = (const float*)d_in[5];
    const float* ln1_b  = (const float*)d_in[6];
    const float* Wffn1  = (const float*)d_in[7];
    const float* bffn1  = (const float*)d_in[8];
    const float* Wffn2  = (const float*)d_in[9];
    const float* bffn2  = (const float*)d_in[10];
    const float* Wqi1   = (const float*)d_in[11];
    const float* Wqi2   = (const float*)d_in[12];
    const float* Wki1   = (const float*)d_in[13];
    const float* Wki2   = (const float*)d_in[14];
    float* out = (float*)d_out;

    float *hr, *q, *k, *v, *attn, *ln, *ff1, *hid, *mid, *raw;
    float *c1, *s1, *c2, *s2;
    cudaGetSymbolAddress((void**)&hr,   g_hr);
    cudaGetSymbolAddress((void**)&q,    g_q);
    cudaGetSymbolAddress((void**)&k,    g_k);
    cudaGetSymbolAddress((void**)&v,    g_v);
    cudaGetSymbolAddress((void**)&attn, g_attn);
    cudaGetSymbolAddress((void**)&ln,   g_ln);
    cudaGetSymbolAddress((void**)&ff1,  g_ff1);
    cudaGetSymbolAddress((void**)&hid,  g_hid);
    cudaGetSymbolAddress((void**)&mid,  g_mid);
    cudaGetSymbolAddress((void**)&raw,  g_raw);
    cudaGetSymbolAddress((void**)&c1,   g_cos1);
    cudaGetSymbolAddress((void**)&s1,   g_sin1);
    cudaGetSymbolAddress((void**)&c2,   g_cos2);
    cudaGetSymbolAddress((void**)&s2,   g_sin2);

    // RoPE tables
    rope_tables_kernel<<<(Lq * DATT + 255) / 256, 256>>>(c1, s1, c2, s2);

    // hr = x @ Wi^T                       [2048,4096]x[1024,4096]^T
    sgemm(x, Wi, nullptr, nullptr, hr, Lq, HRd, Edim, 0);

    // q,k,v
    sgemm(hr, Wq, nullptr, nullptr, q, Lq, HRd, HRd, 0);
    sgemm(hr, Wk, nullptr, nullptr, k, Lq, HRd, HRd, 0);
    sgemm(hr, Wv, nullptr, nullptr, v, Lq, HRd, HRd, 0);

    // RoPE(q,k)
    rope1_kernel<<<(Lq * (HRd / 2) + 255) / 256, 256>>>(q, k, c1, s1);

    // causal attention
    {
        dim3 grid(Lq / 64, Hh);
        attn_kernel<<<grid, 64>>>(q, k, v, attn);
    }

    // LayerNorm
    ln_kernel<<<Lq, 256>>>(attn, ln1_w, ln1_b, ln);

    // FFN
    sgemm(ln,  Wffn1, bffn1, nullptr, ff1, Lq, 2 * HRd, HRd,     1);  // GELU
    sgemm(ff1, Wffn2, bffn2, x,       hid, Lq, Edim,    2 * HRd, 0);  // + residual

    // qi
    sgemm(hid, Wqi1, nullptr, nullptr, mid, Lq, INTD, Edim, 2);       // SiLU
    sgemm(mid, Wqi2, nullptr, nullptr, raw, Lq, Nn * Hh * DD, INTD, 0);
    rope2_out_kernel<<<((Nn * Hh) * Lq * (DD / 2) + 255) / 256, 256>>>(raw, c2, s2, out);

    // ki
    sgemm(hid, Wki1, nullptr, nullptr, mid, Lq, INTD, Edim, 2);       // SiLU
    sgemm(mid, Wki2, nullptr, nullptr, raw, Lq, Nn * Hh * DD, INTD, 0);
    rope2_out_kernel<<<((Nn * Hh) * Lq * (DD / 2) + 255) / 256, 256>>>(
        raw, c2, s2, out + (size_t)(Nn * Hh) * Lq * DD);
    (void)in_sizes; (void)n_in; (void)out_size;
}

// round 10
// speedup vs baseline: 2.0621x; 2.0621x over previous
#include <cuda_runtime.h>
#include <cuda_bf16.h>
#include <cstdint>

// ---------------------------------------------------------------------------
// Problem constants (B=1)
// ---------------------------------------------------------------------------
#define Lq   2048
#define Edim 4096
#define Hh   32
#define Nn   32
#define HRd  1024
#define DATT 32
#define DD   16
#define INTD 1024

// ---------------------------------------------------------------------------
// Scratch (static device globals; no allocation allowed)
// ---------------------------------------------------------------------------
__device__ float g_hr  [Lq * HRd];
__device__ float g_q   [Lq * HRd];
__device__ float g_k   [Lq * HRd];
__device__ float g_v   [Lq * HRd];
__device__ float g_attn[Lq * HRd];
__device__ float g_ln  [Lq * HRd];
__device__ float g_ff1 [Lq * 2 * HRd];
__device__ float g_hid [Lq * Edim];
__device__ float g_mid [Lq * INTD];
__device__ float g_raw [Lq * Nn * Hh * DD];
__device__ float g_cos1[Lq * DATT];
__device__ float g_sin1[Lq * DATT];
__device__ float g_cos2[Lq * DD];
__device__ float g_sin2[Lq * DD];

// ---------------------------------------------------------------------------
// MMA helpers (sm_80-era PTX: compiles on plain sm_103 target)
// ---------------------------------------------------------------------------
__device__ __forceinline__ uint32_t smem_u32(const void* p) {
    uint32_t a;
    asm("{ .reg .u64 t; cvta.to.shared.u64 t, %1; cvt.u32.u64 %0, t; }" : "=r"(a) : "l"(p));
    return a;
}

__device__ __forceinline__ void ldm4(uint32_t* r, uint32_t addr) {
    asm volatile("ldmatrix.sync.aligned.m8n8.x4.shared.b16 {%0,%1,%2,%3}, [%4];"
        : "=r"(r[0]), "=r"(r[1]), "=r"(r[2]), "=r"(r[3]) : "r"(addr));
}

__device__ __forceinline__ void mma16816(float* c, const uint32_t* a, const uint32_t* b) {
    asm volatile(
        "mma.sync.aligned.m16n8k16.row.col.f32.bf16.bf16.f32 "
        "{%0,%1,%2,%3}, {%4,%5,%6,%7}, {%8,%9}, {%0,%1,%2,%3};"
        : "+f"(c[0]), "+f"(c[1]), "+f"(c[2]), "+f"(c[3])
        : "r"(a[0]), "r"(a[1]), "r"(a[2]), "r"(a[3]), "r"(b[0]), "r"(b[1]));
}

// ---------------------------------------------------------------------------
// bf16-split tensor-core GEMM (NT): C[M,N] = act(A[M,K]@B[N,K]^T + bias) + resid
// fp32 = hi(bf16) + lo(bf16);  C += Ahi*Bhi + Ahi*Blo + Alo*Bhi (fp32 acc).
// CTA tile 128x128, K-chunk 32, 8 warps (2x4), warp tile 64x32.
// Smem row stride 80B (odd 16B stride -> conflict-free ldmatrix).
// Requires M%128==0, N%128==0, K%32==0.  act: 0 none, 1 GELU, 2 SiLU
// ---------------------------------------------------------------------------
#define SROW 80
#define TILE_BYTES (128 * SROW)    // 10240

__global__ void __launch_bounds__(256, 2)
tgemm_nt_kernel(const float* __restrict__ A, const float* __restrict__ B,
                const float* __restrict__ bias, const float* __restrict__ resid,
                float* __restrict__ C, int M, int N, int K, int act)
{
    __shared__ alignas(16) char sm[4 * TILE_BYTES];   // Ahi, Alo, Bhi, Blo
    char* aHi = sm;
    char* aLo = sm + TILE_BYTES;
    char* bHi = sm + 2 * TILE_BYTES;
    char* bLo = sm + 3 * TILE_BYTES;

    const int tid = threadIdx.x;
    const int w   = tid >> 5;
    const int l   = tid & 31;
    const int bm  = blockIdx.y * 128;
    const int bn  = blockIdx.x * 128;
    const int warp_m = (w >> 2) * 64;
    const int warp_n = (w & 3) * 32;

    const int lr = tid >> 3;        // 0..31 (row group)
    const int lc = tid & 7;         // 0..7  (float4 col)

    const uint32_t aHiU = smem_u32(aHi), aLoU = smem_u32(aLo);
    const uint32_t bHiU = smem_u32(bHi), bLoU = smem_u32(bLo);

    float acc[4][4][4];
#pragma unroll
    for (int i = 0; i < 4; ++i)
#pragma unroll
        for (int j = 0; j < 4; ++j)
#pragma unroll
            for (int c = 0; c < 4; ++c) acc[i][j][c] = 0.0f;

    const int T = K >> 5;
    for (int t = 0; t < T; ++t) {
        const int k0 = t << 5;

        // ---- load fp32, split to hi/lo bf16, store to smem ----
#pragma unroll
        for (int r4 = 0; r4 < 4; ++r4) {
            const int row = lr + r4 * 32;
            {
                float4 v = *reinterpret_cast<const float4*>(A + (size_t)(bm + row) * K + k0 + lc * 4);
                __nv_bfloat162 h01 = __floats2bfloat162_rn(v.x, v.y);
                __nv_bfloat162 h23 = __floats2bfloat162_rn(v.z, v.w);
                float lx = v.x - __low2float(h01), ly = v.y - __high2float(h01);
                float lz = v.z - __low2float(h23), lw = v.w - __high2float(h23);
                __nv_bfloat162 l01 = __floats2bfloat162_rn(lx, ly);
                __nv_bfloat162 l23 = __floats2bfloat162_rn(lz, lw);
                uint2 hv = { *reinterpret_cast<uint32_t*>(&h01), *reinterpret_cast<uint32_t*>(&h23) };
                uint2 lv = { *reinterpret_cast<uint32_t*>(&l01), *reinterpret_cast<uint32_t*>(&l23) };
                *reinterpret_cast<uint2*>(aHi + row * SROW + lc * 8) = hv;
                *reinterpret_cast<uint2*>(aLo + row * SROW + lc * 8) = lv;
            }
            {
                float4 v = *reinterpret_cast<const float4*>(B + (size_t)(bn + row) * K + k0 + lc * 4);
                __nv_bfloat162 h01 = __floats2bfloat162_rn(v.x, v.y);
                __nv_bfloat162 h23 = __floats2bfloat162_rn(v.z, v.w);
                float lx = v.x - __low2float(h01), ly = v.y - __high2float(h01);
                float lz = v.z - __low2float(h23), lw = v.w - __high2float(h23);
                __nv_bfloat162 l01 = __floats2bfloat162_rn(lx, ly);
                __nv_bfloat162 l23 = __floats2bfloat162_rn(lz, lw);
                uint2 hv = { *reinterpret_cast<uint32_t*>(&h01), *reinterpret_cast<uint32_t*>(&h23) };
                uint2 lv = { *reinterpret_cast<uint32_t*>(&l01), *reinterpret_cast<uint32_t*>(&l23) };
                *reinterpret_cast<uint2*>(bHi + row * SROW + lc * 8) = hv;
                *reinterpret_cast<uint2*>(bLo + row * SROW + lc * 8) = lv;
            }
        }
        __syncthreads();

        // ---- tensor-core phase: 2 x k16 steps, 3 split terms each ----
#pragma unroll
        for (int ks = 0; ks < 2; ++ks) {
            const int ko = ks * 16;
            // fragment smem addresses (bytes)
            const uint32_t aoff = (uint32_t)(warp_m + (l & 15)) * SROW + (uint32_t)(ko + (l >> 4) * 8) * 2;
            const uint32_t boff0 = (uint32_t)(warp_n + (l & 7) + ((l >> 4) << 3)) * SROW +
                                   (uint32_t)(ko + ((l >> 3) & 1) * 8) * 2;

            uint32_t af[4][4], bh[2][4], bl[2][4];
#pragma unroll
            for (int i = 0; i < 4; ++i) ldm4(af[i], aHiU + aoff + (uint32_t)(i * 16) * SROW);
#pragma unroll
            for (int p = 0; p < 2; ++p) ldm4(bh[p], bHiU + boff0 + (uint32_t)(p * 16) * SROW);

            // term 1: Ahi * Bhi
#pragma unroll
            for (int i = 0; i < 4; ++i)
#pragma unroll
                for (int j = 0; j < 4; ++j)
                    mma16816(acc[i][j], af[i], &bh[j >> 1][(j & 1) * 2]);

            // term 2: Ahi * Blo
#pragma unroll
            for (int p = 0; p < 2; ++p) ldm4(bl[p], bLoU + boff0 + (uint32_t)(p * 16) * SROW);
#pragma unroll
            for (int i = 0; i < 4; ++i)
#pragma unroll
                for (int j = 0; j < 4; ++j)
                    mma16816(acc[i][j], af[i], &bl[j >> 1][(j & 1) * 2]);

            // term 3: Alo * Bhi
#pragma unroll
            for (int i = 0; i < 4; ++i) ldm4(af[i], aLoU + aoff + (uint32_t)(i * 16) * SROW);
#pragma unroll
            for (int i = 0; i < 4; ++i)
#pragma unroll
                for (int j = 0; j < 4; ++j)
                    mma16816(acc[i][j], af[i], &bh[j >> 1][(j & 1) * 2]);
        }
        __syncthreads();
    }

    // ---- epilogue ----
#pragma unroll
    for (int i = 0; i < 4; ++i) {
#pragma unroll
        for (int j = 0; j < 4; ++j) {
            const int n0 = bn + warp_n + j * 8 + (l & 3) * 2;
#pragma unroll
            for (int half = 0; half < 2; ++half) {
                const int m = bm + warp_m + i * 16 + (l >> 2) + half * 8;
                float v0 = acc[i][j][half * 2 + 0];
                float v1 = acc[i][j][half * 2 + 1];
                if (bias) { v0 += bias[n0]; v1 += bias[n0 + 1]; }
                if (act == 1) {
                    v0 = 0.5f * v0 * (1.0f + erff(v0 * 0.7071067811865475f));
                    v1 = 0.5f * v1 * (1.0f + erff(v1 * 0.7071067811865475f));
                } else if (act == 2) {
                    v0 = v0 / (1.0f + expf(-v0));
                    v1 = v1 / (1.0f + expf(-v1));
                }
                if (resid) {
                    v0 += resid[(size_t)m * N + n0];
                    v1 += resid[(size_t)m * N + n0 + 1];
                }
                float2 o = make_float2(v0, v1);
                *reinterpret_cast<float2*>(C + (size_t)m * N + n0) = o;
            }
        }
    }
}

// ---------------------------------------------------------------------------
// RoPE tables (match reference fp32 math)
// ---------------------------------------------------------------------------
__global__ void rope_tables_kernel(float* __restrict__ c1, float* __restrict__ s1,
                                   float* __restrict__ c2, float* __restrict__ s2)
{
    int idx = blockIdx.x * blockDim.x + threadIdx.x;
    if (idx < Lq * DATT) {
        int l = idx / DATT, d = idx % DATT;
        float inv = 1.0f / powf(10000.0f, (float)(2 * (d & 15)) / 32.0f);
        float f = (float)l * inv;
        c1[idx] = cosf(f);
        s1[idx] = sinf(f);
    }
    if (idx < Lq * DD) {
        int l = idx / DD, d = idx % DD;
        float inv = 1.0f / powf(10000.0f, (float)(2 * (d & 7)) / 16.0f);
        float f = (float)l * inv;
        c2[idx] = cosf(f);
        s2[idx] = sinf(f);
    }
}

// ---------------------------------------------------------------------------
// RoPE on q,k (head dim 32), in place
// ---------------------------------------------------------------------------
__global__ void rope1_kernel(float* __restrict__ q, float* __restrict__ k,
                             const float* __restrict__ c1, const float* __restrict__ s1)
{
    int idx = blockIdx.x * blockDim.x + threadIdx.x;
    if (idx >= Lq * (HRd / 2)) return;
    int l = idx >> 9;
    int c = idx & 511;
    int h = c >> 4;
    int d = c & 15;
    int base = l * HRd + h * DATT;
    float cv = c1[l * DATT + d];
    float sv = s1[l * DATT + d];

    float a  = q[base + d];
    float b  = q[base + d + 16];
    q[base + d]      = a * cv - b * sv;
    q[base + d + 16] = b * cv + a * sv;

    float a2 = k[base + d];
    float b2 = k[base + d + 16];
    k[base + d]      = a2 * cv - b2 * sv;
    k[base + d + 16] = b2 * cv + a2 * sv;
}

// ---------------------------------------------------------------------------
// Causal flash attention, d=32, thread-per-query online softmax
// ---------------------------------------------------------------------------
__global__ void __launch_bounds__(64)
attn_kernel(const float* __restrict__ Q, const float* __restrict__ Kg,
            const float* __restrict__ Vg, float* __restrict__ O)
{
    __shared__ float Ks[64][32];
    __shared__ float Vs[64][32];

    const int h  = blockIdx.y;
    const int qb = blockIdx.x;
    const int t  = threadIdx.x;
    const int qrow = qb * 64 + t;

    float qreg[32], acc[32];
    const float* qp = Q + (size_t)qrow * HRd + h * DATT;
#pragma unroll
    for (int d = 0; d < 32; ++d) { qreg[d] = qp[d]; acc[d] = 0.0f; }

    float m = -1e30f, lsum = 0.0f;
    const float scale = 0.17677669529663687f;

    for (int kt = 0; kt <= qb; ++kt) {
        for (int idx = t; idx < 64 * 8; idx += 64) {
            int r  = idx / 8;
            int c4 = (idx % 8) * 4;
            size_t g = (size_t)(kt * 64 + r) * HRd + h * DATT + c4;
            *reinterpret_cast<float4*>(&Ks[r][c4]) = *reinterpret_cast<const float4*>(&Kg[g]);
            *reinterpret_cast<float4*>(&Vs[r][c4]) = *reinterpret_cast<const float4*>(&Vg[g]);
        }
        __syncthreads();

        const int kmax = (kt == qb) ? (t + 1) : 64;
        for (int kk = 0; kk < kmax; ++kk) {
            float s = 0.0f;
#pragma unroll
            for (int d = 0; d < 32; ++d) s += qreg[d] * Ks[kk][d];
            s *= scale;
            float mnew = fmaxf(m, s);
            float corr = __expf(m - mnew);
            float p    = __expf(s - mnew);
            lsum = lsum * corr + p;
#pragma unroll
            for (int d = 0; d < 32; ++d) acc[d] = acc[d] * corr + p * Vs[kk][d];
            m = mnew;
        }
        __syncthreads();
    }

    float inv = 1.0f / lsum;
    float* op = O + (size_t)qrow * HRd + h * DATT;
#pragma unroll
    for (int d = 0; d < 32; ++d) op[d] = acc[d] * inv;
}

// ---------------------------------------------------------------------------
// LayerNorm over last dim (1024)
// ---------------------------------------------------------------------------
__global__ void __launch_bounds__(256)
ln_kernel(const float* __restrict__ X, const float* __restrict__ w,
          const float* __restrict__ b, float* __restrict__ Y)
{
    __shared__ float red[256];
    const int row = blockIdx.x;
    const float* xr = X + (size_t)row * HRd;

    float s = 0.0f;
    for (int i = threadIdx.x; i < HRd; i += 256) s += xr[i];
    red[threadIdx.x] = s; __syncthreads();
    for (int st = 128; st > 0; st >>= 1) {
        if (threadIdx.x < st) red[threadIdx.x] += red[threadIdx.x + st];
        __syncthreads();
    }
    float mu = red[0] / (float)HRd;
    __syncthreads();

    float vs = 0.0f;
    for (int i = threadIdx.x; i < HRd; i += 256) { float d = xr[i] - mu; vs += d * d; }
    red[threadIdx.x] = vs; __syncthreads();
    for (int st = 128; st > 0; st >>= 1) {
        if (threadIdx.x < st) red[threadIdx.x] += red[threadIdx.x + st];
        __syncthreads();
    }
    float rstd = rsqrtf(red[0] / (float)HRd + 1e-5f);

    for (int i = threadIdx.x; i < HRd; i += 256)
        Y[(size_t)row * HRd + i] = (xr[i] - mu) * rstd * w[i] + b[i];
}

// ---------------------------------------------------------------------------
// Second RoPE (dim 16) fused with the [L, N*H*16] -> [N,H,L,16] permute
// ---------------------------------------------------------------------------
__global__ void rope2_out_kernel(const float* __restrict__ P,
                                 const float* __restrict__ c2, const float* __restrict__ s2,
                                 float* __restrict__ out)
{
    int idx = blockIdx.x * blockDim.x + threadIdx.x;
    if (idx >= (Nn * Hh) * Lq * (DD / 2)) return;
    int d = idx & 7;
    int l = (idx >> 3) & (Lq - 1);
    int r = idx >> 14;

    const float* p = P + (size_t)l * (Nn * Hh * DD) + r * DD;
    float a = p[d], b = p[d + 8];
    float cv = c2[l * DD + d];
    float sv = s2[l * DD + d];

    size_t o = ((size_t)r * Lq + l) * DD;
    out[o + d]     = a * cv - b * sv;
    out[o + d + 8] = b * cv + a * sv;
}

// ---------------------------------------------------------------------------
// Launch
// ---------------------------------------------------------------------------
static void tgemm(const float* A, const float* B, const float* bias,
                  const float* resid, float* C, int M, int N, int K, int act)
{
    dim3 grid(N / 128, M / 128);
    tgemm_nt_kernel<<<grid, 256>>>(A, B, bias, resid, C, M, N, K, act);
}

extern "C" void kernel_launch(void* const* d_in, const int* in_sizes, int n_in,
                              void* d_out, int out_size)
{
    const float* x      = (const float*)d_in[0];
    const float* Wi     = (const float*)d_in[1];
    const float* Wq     = (const float*)d_in[2];
    const float* Wk     = (const float*)d_in[3];
    const float* Wv     = (const float*)d_in[4];
    const float* ln1_w  = (const float*)d_in[5];
    const float* ln1_b  = (const float*)d_in[6];
    const float* Wffn1  = (const float*)d_in[7];
    const float* bffn1  = (const float*)d_in[8];
    const float* Wffn2  = (const float*)d_in[9];
    const float* bffn2  = (const float*)d_in[10];
    const float* Wqi1   = (const float*)d_in[11];
    const float* Wqi2   = (const float*)d_in[12];
    const float* Wki1   = (const float*)d_in[13];
    const float* Wki2   = (const float*)d_in[14];
    float* out = (float*)d_out;

    float *hr, *q, *k, *v, *attn, *ln, *ff1, *hid, *mid, *raw;
    float *c1, *s1, *c2, *s2;
    cudaGetSymbolAddress((void**)&hr,   g_hr);
    cudaGetSymbolAddress((void**)&q,    g_q);
    cudaGetSymbolAddress((void**)&k,    g_k);
    cudaGetSymbolAddress((void**)&v,    g_v);
    cudaGetSymbolAddress((void**)&attn, g_attn);
    cudaGetSymbolAddress((void**)&ln,   g_ln);
    cudaGetSymbolAddress((void**)&ff1,  g_ff1);
    cudaGetSymbolAddress((void**)&hid,  g_hid);
    cudaGetSymbolAddress((void**)&mid,  g_mid);
    cudaGetSymbolAddress((void**)&raw,  g_raw);
    cudaGetSymbolAddress((void**)&c1,   g_cos1);
    cudaGetSymbolAddress((void**)&s1,   g_sin1);
    cudaGetSymbolAddress((void**)&c2,   g_cos2);
    cudaGetSymbolAddress((void**)&s2,   g_sin2);

    rope_tables_kernel<<<(Lq * DATT + 255) / 256, 256>>>(c1, s1, c2, s2);

    tgemm(x, Wi, nullptr, nullptr, hr, Lq, HRd, Edim, 0);

    tgemm(hr, Wq, nullptr, nullptr, q, Lq, HRd, HRd, 0);
    tgemm(hr, Wk, nullptr, nullptr, k, Lq, HRd, HRd, 0);
    tgemm(hr, Wv, nullptr, nullptr, v, Lq, HRd, HRd, 0);

    rope1_kernel<<<(Lq * (HRd / 2) + 255) / 256, 256>>>(q, k, c1, s1);

    {
        dim3 grid(Lq / 64, Hh);
        attn_kernel<<<grid, 64>>>(q, k, v, attn);
    }

    ln_kernel<<<Lq, 256>>>(attn, ln1_w, ln1_b, ln);

    tgemm(ln,  Wffn1, bffn1, nullptr, ff1, Lq, 2 * HRd, HRd,     1);  // GELU
    tgemm(ff1, Wffn2, bffn2, x,       hid, Lq, Edim,    2 * HRd, 0);  // + residual

    tgemm(hid, Wqi1, nullptr, nullptr, mid, Lq, INTD, Edim, 2);       // SiLU
    tgemm(mid, Wqi2, nullptr, nullptr, raw, Lq, Nn * Hh * DD, INTD, 0);
    rope2_out_kernel<<<((Nn * Hh) * Lq * (DD / 2) + 255) / 256, 256>>>(raw, c2, s2, out);

    tgemm(hid, Wki1, nullptr, nullptr, mid, Lq, INTD, Edim, 2);       // SiLU
    tgemm(mid, Wki2, nullptr, nullptr, raw, Lq, Nn * Hh * DD, INTD, 0);
    rope2_out_kernel<<<((Nn * Hh) * Lq * (DD / 2) + 255) / 256, 256>>>(
        raw, c2, s2, out + (size_t)(Nn * Hh) * Lq * DD);
    (void)in_sizes; (void)n_in; (void)out_size;
}